// round 7
// baseline (speedup 1.0000x reference)
#include <cuda_runtime.h>
#include <cstdint>

// ---------------------------------------------------------------------------
// Problem dims
// ---------------------------------------------------------------------------
#define HW        128
#define OW        126
#define LIN       15876              // (128-2)^2
#define K_TILE    64
#define N_KTILES  252                // LIN_PAD = 16128
#define LIN_PAD   (N_KTILES * K_TILE)
#define TRI       8256
#define BATCH     64
#define NDIM      128
#define T_PAD     8320               // 65*128
#define N_MTILES  65
#define KSPLIT    2
#define TILES_PER_SPLIT (N_KTILES / KSPLIT)   // 126

#define QF        32639.0f           // 15-bit quant full-scale (hi/lo split safe)

// SMEM layout, pitch 80 B (odd multiple of 16 -> conflict-free ldmatrix)
// A stage: hi 128x80 = 10240, lo 10240, row scales 512  -> 20992 per stage, x2
// B stage: hi  64x80 =  5120, lo  5120                  -> 10240 per stage, x3
#define PITCH     80
#define A_HI(s)   ((uint32_t)(s) * 20992u)
#define A_LO(s)   (A_HI(s) + 10240u)
#define A_SC(s)   (A_HI(s) + 20480u)
#define B_HI(st)  (41984u + (uint32_t)(st) * 10240u)
#define B_LO(st)  (B_HI(st) + 5120u)
#define SMEM_BYTES 72704

// ---------------------------------------------------------------------------
// Scratch (device globals — no allocation allowed)
// ---------------------------------------------------------------------------
__device__ float    g_h[(size_t)BATCH * LIN_PAD];       // conv output fp32
__device__ int8_t   g_hb_hi[(size_t)BATCH * LIN_PAD];   // [b][l] int8 hi
__device__ int8_t   g_hb_lo[(size_t)BATCH * LIN_PAD];   // [b][l] int8 lo
__device__ float    g_vp[(size_t)KSPLIT * BATCH * T_PAD];
__device__ unsigned g_maxh;   // |h| max as fp32 bits (idempotent across runs)

// ---------------------------------------------------------------------------
// helpers
// ---------------------------------------------------------------------------
__device__ __forceinline__ uint32_t smem_u32(const void* p) {
    uint32_t a;
    asm("{ .reg .u64 t; cvta.to.shared.u64 t, %1; cvt.u32.u64 %0, t; }"
        : "=r"(a) : "l"(p));
    return a;
}

__device__ __forceinline__ void cp_async16(uint32_t dst, const void* src) {
    asm volatile("cp.async.cg.shared.global [%0], [%1], 16;"
                 :: "r"(dst), "l"(src) : "memory");
}
__device__ __forceinline__ void cp_commit() {
    asm volatile("cp.async.commit_group;" ::: "memory");
}
template <int N>
__device__ __forceinline__ void cp_wait() {
    asm volatile("cp.async.wait_group %0;" :: "n"(N) : "memory");
}

__device__ __forceinline__ void ldsm4(uint32_t& r0, uint32_t& r1,
                                      uint32_t& r2, uint32_t& r3, uint32_t addr) {
    asm volatile("ldmatrix.sync.aligned.m8n8.x4.shared.b16 {%0,%1,%2,%3}, [%4];"
                 : "=r"(r0), "=r"(r1), "=r"(r2), "=r"(r3) : "r"(addr));
}

__device__ __forceinline__ void mma_s8(int* c,
                                       uint32_t a0, uint32_t a1, uint32_t a2, uint32_t a3,
                                       uint32_t b0, uint32_t b1) {
    asm volatile(
        "mma.sync.aligned.m16n8k32.row.col.s32.s8.s8.s32 "
        "{%0,%1,%2,%3}, {%4,%5,%6,%7}, {%8,%9}, {%0,%1,%2,%3};"
        : "+r"(c[0]), "+r"(c[1]), "+r"(c[2]), "+r"(c[3])
        : "r"(a0), "r"(a1), "r"(a2), "r"(a3), "r"(b0), "r"(b1));
}

// ---------------------------------------------------------------------------
// Kernel 1: fused conv -> fp32 h + global |h| max (atomicMax on fp bits)
// grid exactly divides: 64*16128/256 = 4032 blocks, no stragglers
// ---------------------------------------------------------------------------
__global__ void conv_fuse_kernel(const float* __restrict__ x,
                                 const float* __restrict__ w1,
                                 const float* __restrict__ b1,
                                 const float* __restrict__ w2,
                                 const float* __restrict__ b2) {
    int idx = blockIdx.x * blockDim.x + threadIdx.x;
    int b = idx / LIN_PAD;
    int l = idx - b * LIN_PAD;

    float val = 0.0f;
    if (l < LIN) {
        int i = l / OW;
        int j = l - i * OW;
        const float* xp = x + (size_t)b * (HW * HW) + i * HW + j;
        float acc = b2[0];
        #pragma unroll
        for (int c = 0; c < 4; c++) {
            float s = b1[c];
            #pragma unroll
            for (int di = 0; di < 3; di++)
                #pragma unroll
                for (int dj = 0; dj < 3; dj++)
                    s = fmaf(xp[di * HW + dj], w1[c * 9 + di * 3 + dj], s);
            acc = fmaf(w2[c], fmaxf(s, 0.0f), acc);
        }
        val = acc;
    }
    g_h[idx] = val;

    // block max |val| -> atomicMax (positive floats compare as uints)
    float am = fabsf(val);
    #pragma unroll
    for (int off = 16; off > 0; off >>= 1)
        am = fmaxf(am, __shfl_xor_sync(0xFFFFFFFFu, am, off));
    __shared__ float wmax[8];
    int wid = threadIdx.x >> 5;
    if ((threadIdx.x & 31) == 0) wmax[wid] = am;
    __syncthreads();
    if (threadIdx.x == 0) {
        float m = wmax[0];
        #pragma unroll
        for (int w = 1; w < 8; w++) m = fmaxf(m, wmax[w]);
        atomicMax(&g_maxh, __float_as_uint(m));
    }
}

// ---------------------------------------------------------------------------
// Kernel 1b: quantize h -> int8 hi/lo (15-bit fixed point, global scale)
// ---------------------------------------------------------------------------
__global__ void quant_h_kernel() {
    int t = blockIdx.x * blockDim.x + threadIdx.x;   // 258048 threads, x4 vals
    float r = QF / fmaxf(__uint_as_float(g_maxh), 1e-30f);
    float4 h4 = *reinterpret_cast<const float4*>(g_h + (size_t)t * 4);
    int v0 = __float2int_rn(h4.x * r);
    int v1 = __float2int_rn(h4.y * r);
    int v2 = __float2int_rn(h4.z * r);
    int v3 = __float2int_rn(h4.w * r);
    int h0 = (v0 + 128) >> 8, h1 = (v1 + 128) >> 8;
    int h2 = (v2 + 128) >> 8, h3 = (v3 + 128) >> 8;
    int l0 = v0 - (h0 << 8), l1 = v1 - (h1 << 8);
    int l2 = v2 - (h2 << 8), l3 = v3 - (h3 << 8);
    uint32_t hp = (h0 & 0xFF) | ((h1 & 0xFF) << 8) | ((h2 & 0xFF) << 16) | (h3 << 24);
    uint32_t lp = (l0 & 0xFF) | ((l1 & 0xFF) << 8) | ((l2 & 0xFF) << 16) | (l3 << 24);
    *reinterpret_cast<uint32_t*>(g_hb_hi + (size_t)t * 4) = hp;
    *reinterpret_cast<uint32_t*>(g_hb_lo + (size_t)t * 4) = lp;
}

// ---------------------------------------------------------------------------
// GEMM device helpers (512 threads: arow = tid>>2, aq = tid&3)
// ---------------------------------------------------------------------------
__device__ __forceinline__ void ldg_a(const float* __restrict__ W,
                                      int t, int l0, int aq, bool trow_ok,
                                      float4 (&a)[4]) {
    #pragma unroll
    for (int j = 0; j < 4; j++) {
        int l = l0 + (aq * 4 + j) * 4;
        if (trow_ok && l < LIN)
            a[j] = *reinterpret_cast<const float4*>(W + (size_t)t * LIN + l);
        else
            a[j] = make_float4(0.f, 0.f, 0.f, 0.f);
    }
}

// quantize row chunk (64 vals across 4 threads) + STS int8 hi/lo + row scale
__device__ __forceinline__ void sts_a_q(char* smem, int stage, int row, int aq,
                                        const float4 (&a)[4]) {
    float m = 0.f;
    #pragma unroll
    for (int j = 0; j < 4; j++) {
        m = fmaxf(m, fmaxf(fmaxf(fabsf(a[j].x), fabsf(a[j].y)),
                           fmaxf(fabsf(a[j].z), fabsf(a[j].w))));
    }
    m = fmaxf(m, __shfl_xor_sync(0xFFFFFFFFu, m, 1));
    m = fmaxf(m, __shfl_xor_sync(0xFFFFFFFFu, m, 2));
    float r = QF / fmaxf(m, 1e-30f);

    uint32_t hiP[4], loP[4];
    #pragma unroll
    for (int j = 0; j < 4; j++) {
        int v0 = __float2int_rn(a[j].x * r);
        int v1 = __float2int_rn(a[j].y * r);
        int v2 = __float2int_rn(a[j].z * r);
        int v3 = __float2int_rn(a[j].w * r);
        int h0 = (v0 + 128) >> 8, h1 = (v1 + 128) >> 8;
        int h2 = (v2 + 128) >> 8, h3 = (v3 + 128) >> 8;
        int l0 = v0 - (h0 << 8), l1 = v1 - (h1 << 8);
        int l2 = v2 - (h2 << 8), l3 = v3 - (h3 << 8);
        hiP[j] = (h0 & 0xFF) | ((h1 & 0xFF) << 8) | ((h2 & 0xFF) << 16) | (h3 << 24);
        loP[j] = (l0 & 0xFF) | ((l1 & 0xFF) << 8) | ((l2 & 0xFF) << 16) | (l3 << 24);
    }
    uint32_t byt = (uint32_t)row * PITCH + (uint32_t)aq * 16;
    *reinterpret_cast<uint4*>(smem + A_HI(stage) + byt) =
        make_uint4(hiP[0], hiP[1], hiP[2], hiP[3]);
    *reinterpret_cast<uint4*>(smem + A_LO(stage) + byt) =
        make_uint4(loP[0], loP[1], loP[2], loP[3]);
    if (aq == 0)
        *reinterpret_cast<float*>(smem + A_SC(stage) + (uint32_t)row * 4) =
            m * (1.0f / QF);
}

__device__ __forceinline__ void cpasync_b(uint32_t sb, int st, int ktg, int tid) {
    int l0 = ktg * K_TILE;
    int id  = tid & 255;
    int row = id >> 2;                           // batch 0..63
    int ch  = id & 3;                            // 16B chunk
    uint32_t byt = (uint32_t)row * PITCH + (uint32_t)ch * 16;
    if (tid < 256)
        cp_async16(sb + B_HI(st) + byt, g_hb_hi + (size_t)row * LIN_PAD + l0 + ch * 16);
    else
        cp_async16(sb + B_LO(st) + byt, g_hb_lo + (size_t)row * LIN_PAD + l0 + ch * 16);
}

// warp tile: 32 rows (wm) x 16 cols (wn); int8 MMA k32, 2 ksteps
__device__ __forceinline__ void compute_tile_i8(char* smem, uint32_t sb,
                                                int stage, int bst,
                                                int wm, int wn, int lid,
                                                float sH, float (&accf)[2][2][4]) {
    int p1[2][2][4], p2[2][2][4];
    #pragma unroll
    for (int mt = 0; mt < 2; mt++)
        #pragma unroll
        for (int nt = 0; nt < 2; nt++)
            #pragma unroll
            for (int e = 0; e < 4; e++) { p1[mt][nt][e] = 0; p2[mt][nt][e] = 0; }

    const uint32_t lrow = (uint32_t)(lid & 15);
    const uint32_t lhi  = (uint32_t)((lid >> 4) << 4);

    uint32_t aH0 = sb + A_HI(stage) + (wm * 32 + lrow) * PITCH + lhi;
    uint32_t aH1 = aH0 + 16 * PITCH;
    uint32_t aL0 = sb + A_LO(stage) + (wm * 32 + lrow) * PITCH + lhi;
    uint32_t aL1 = aL0 + 16 * PITCH;
    uint32_t bH  = sb + B_HI(bst) + (wn * 16 + lrow) * PITCH + lhi;
    uint32_t bL  = sb + B_LO(bst) + (wn * 16 + lrow) * PITCH + lhi;

    #pragma unroll
    for (int ks = 0; ks < 2; ks++) {
        const uint32_t ko = (uint32_t)ks * 32;   // 32 int8 per kstep

        uint32_t ah[2][4], al[2][4];
        ldsm4(ah[0][0], ah[0][1], ah[0][2], ah[0][3], aH0 + ko);
        ldsm4(ah[1][0], ah[1][1], ah[1][2], ah[1][3], aH1 + ko);
        ldsm4(al[0][0], al[0][1], al[0][2], al[0][3], aL0 + ko);
        ldsm4(al[1][0], al[1][1], al[1][2], al[1][3], aL1 + ko);

        uint32_t b0, b1, b2, b3, c0, c1, c2, c3;
        ldsm4(b0, b1, b2, b3, bH + ko);
        ldsm4(c0, c1, c2, c3, bL + ko);
        uint32_t bh[2][2] = {{b0, b2}, {b1, b3}};
        uint32_t bl[2][2] = {{c0, c2}, {c1, c3}};

        #pragma unroll
        for (int mt = 0; mt < 2; mt++)
            #pragma unroll
            for (int nt = 0; nt < 2; nt++) {
                mma_s8(p1[mt][nt], ah[mt][0], ah[mt][1], ah[mt][2], ah[mt][3],
                       bh[nt][0], bh[nt][1]);
                mma_s8(p2[mt][nt], ah[mt][0], ah[mt][1], ah[mt][2], ah[mt][3],
                       bl[nt][0], bl[nt][1]);
                mma_s8(p2[mt][nt], al[mt][0], al[mt][1], al[mt][2], al[mt][3],
                       bh[nt][0], bh[nt][1]);
            }
    }

    // per-tile fp32 fixup with per-row W scale * global h scale
    const int g = lid >> 2;
    #pragma unroll
    for (int mt = 0; mt < 2; mt++) {
        int r0 = wm * 32 + mt * 16 + g;
        float s0 = *reinterpret_cast<const float*>(smem + A_SC(stage) + r0 * 4) * sH;
        float s8v = *reinterpret_cast<const float*>(smem + A_SC(stage) + (r0 + 8) * 4) * sH;
        #pragma unroll
        for (int nt = 0; nt < 2; nt++) {
            accf[mt][nt][0] += s0  * fmaf(65536.0f, (float)p1[mt][nt][0], 256.0f * (float)p2[mt][nt][0]);
            accf[mt][nt][1] += s0  * fmaf(65536.0f, (float)p1[mt][nt][1], 256.0f * (float)p2[mt][nt][1]);
            accf[mt][nt][2] += s8v * fmaf(65536.0f, (float)p1[mt][nt][2], 256.0f * (float)p2[mt][nt][2]);
            accf[mt][nt][3] += s8v * fmaf(65536.0f, (float)p1[mt][nt][3], 256.0f * (float)p2[mt][nt][3]);
        }
    }
}

// ---------------------------------------------------------------------------
// Kernel 2: int8-split IMMA GEMM, 130 CTAs x 512 threads (16 warps)
// ---------------------------------------------------------------------------
__global__ __launch_bounds__(512, 1)
void gemm_tc_kernel(const float* __restrict__ W) {
    extern __shared__ char smem[];
    const uint32_t sb = smem_u32(smem);

    const int tid = threadIdx.x;
    const int wid = tid >> 5;
    const int lid = tid & 31;
    const int g   = lid >> 2;
    const int t4  = lid & 3;
    const int wm  = wid & 3;        // 4 row groups x 32
    const int wn  = wid >> 2;       // 4 col groups x 16

    const int mtile = blockIdx.x >> 1;
    const int split = blockIdx.x & 1;
    const int t0    = mtile * 128;
    const int kt0   = split * TILES_PER_SPLIT;

    const int arow  = tid >> 2;
    const int aq    = tid & 3;
    const int atrow = t0 + arow;
    const bool trow_ok = (atrow < TRI);

    const float sH = __uint_as_float(g_maxh) * (1.0f / QF);

    float accf[2][2][4];
    #pragma unroll
    for (int i = 0; i < 2; i++)
        #pragma unroll
        for (int j = 0; j < 2; j++)
            #pragma unroll
            for (int k = 0; k < 4; k++)
                accf[i][j][k] = 0.f;

    float4 aR[4];

    // ---- prologue ----
    cpasync_b(sb, 0, kt0 + 0, tid);
    cp_commit();
    cpasync_b(sb, 1, kt0 + 1, tid);
    cp_commit();
    ldg_a(W, atrow, (kt0 + 0) * K_TILE, aq, trow_ok, aR);
    sts_a_q(smem, 0, arow, aq, aR);
    ldg_a(W, atrow, (kt0 + 1) * K_TILE, aq, trow_ok, aR);
    cp_wait<1>();
    __syncthreads();

    int bs = 0;
    for (int kt = 0; kt < TILES_PER_SPLIT; kt++) {
        const int nxt_bs = (bs + 2 >= 3) ? bs - 1 : bs + 2;

        if (kt + 2 < TILES_PER_SPLIT) {
            cpasync_b(sb, nxt_bs, kt0 + kt + 2, tid);
            cp_commit();
        }
        if (kt + 1 < TILES_PER_SPLIT)
            sts_a_q(smem, (kt + 1) & 1, arow, aq, aR);
        if (kt + 2 < TILES_PER_SPLIT)
            ldg_a(W, atrow, (kt0 + kt + 2) * K_TILE, aq, trow_ok, aR);

        compute_tile_i8(smem, sb, kt & 1, bs, wm, wn, lid, sH, accf);

        if (kt + 2 < TILES_PER_SPLIT)      cp_wait<1>();
        else if (kt + 1 < TILES_PER_SPLIT) cp_wait<0>();
        __syncthreads();

        bs = (bs + 1 >= 3) ? 0 : bs + 1;
    }

    // ---- epilogue ----
    float* vp = g_vp + (size_t)split * BATCH * T_PAD;
    #pragma unroll
    for (int mt = 0; mt < 2; mt++) {
        #pragma unroll
        for (int nt = 0; nt < 2; nt++) {
            int r  = t0 + wm * 32 + mt * 16 + g;
            int cb = wn * 16 + nt * 8 + 2 * t4;
            vp[(size_t)cb       * T_PAD + r]     = accf[mt][nt][0];
            vp[(size_t)(cb + 1) * T_PAD + r]     = accf[mt][nt][1];
            vp[(size_t)cb       * T_PAD + r + 8] = accf[mt][nt][2];
            vp[(size_t)(cb + 1) * T_PAD + r + 8] = accf[mt][nt][3];
        }
    }
}

// ---------------------------------------------------------------------------
// Kernel 3: symmetric triu scatter + split-K reduce + bias
// ---------------------------------------------------------------------------
__global__ void scatter_kernel(float* __restrict__ out,
                               const float* __restrict__ bias) {
    int idx = blockIdx.x * blockDim.x + threadIdx.x;
    if (idx >= BATCH * NDIM * NDIM) return;
    int b = idx >> 14;
    int r = (idx >> 7) & 127;
    int c = idx & 127;
    int i = min(r, c);
    int j = max(r, c);
    int t = i * NDIM - (i * (i - 1)) / 2 + (j - i);
    out[idx] = g_vp[(size_t)b * T_PAD + t] +
               g_vp[(size_t)(BATCH + b) * T_PAD + t] + bias[t];
}

// ---------------------------------------------------------------------------
extern "C" void kernel_launch(void* const* d_in, const int* in_sizes, int n_in,
                              void* d_out, int out_size) {
    const float* x       = (const float*)d_in[0];
    const float* conv1_w = (const float*)d_in[1];
    const float* conv1_b = (const float*)d_in[2];
    const float* conv2_w = (const float*)d_in[3];
    const float* conv2_b = (const float*)d_in[4];
    const float* out_w   = (const float*)d_in[5];
    const float* out_b   = (const float*)d_in[6];
    float* out = (float*)d_out;

    cudaFuncSetAttribute(gemm_tc_kernel,
                         cudaFuncAttributeMaxDynamicSharedMemorySize, SMEM_BYTES);

    conv_fuse_kernel<<<(BATCH * LIN_PAD) / 256, 256>>>(x, conv1_w, conv1_b,
                                                       conv2_w, conv2_b);
    quant_h_kernel<<<(BATCH * LIN_PAD / 4) / 256, 256>>>();
    gemm_tc_kernel<<<N_MTILES * KSPLIT, 512, SMEM_BYTES>>>(out_w);
    scatter_kernel<<<(BATCH * NDIM * NDIM + 255) / 256, 256>>>(out, out_b);
}

// round 8
// speedup vs baseline: 1.0001x; 1.0001x over previous
#include <cuda_runtime.h>
#include <cstdint>

// ---------------------------------------------------------------------------
// Problem dims
// ---------------------------------------------------------------------------
#define HW        128
#define OW        126
#define LIN       15876              // (128-2)^2
#define K_TILE    64
#define N_KTILES  252                // LIN_PAD = 16128
#define LIN_PAD   (N_KTILES * K_TILE)
#define TRI       8256
#define BATCH     64
#define NDIM      128
#define T_PAD     8320               // 65*128
#define N_MTILES  65
#define KSPLIT    2
#define TILES_PER_SPLIT (N_KTILES / KSPLIT)   // 126

#define QF        32639.0f           // 15-bit quant full-scale (hi/lo split safe)

// SMEM layout, pitch 80 B (odd multiple of 16 -> conflict-free ldmatrix)
// A stage: hi 128x80 = 10240, lo 10240, row scales 512  -> 20992 per stage, x2
// B stage: hi  64x80 =  5120, lo  5120                  -> 10240 per stage, x3
#define PITCH     80
#define A_HI(s)   ((uint32_t)(s) * 20992u)
#define A_LO(s)   (A_HI(s) + 10240u)
#define A_SC(s)   (A_HI(s) + 20480u)
#define B_HI(st)  (41984u + (uint32_t)(st) * 10240u)
#define B_LO(st)  (B_HI(st) + 5120u)
#define SMEM_BYTES 72704

// ---------------------------------------------------------------------------
// Scratch (device globals — no allocation allowed)
// ---------------------------------------------------------------------------
__device__ float    g_h[(size_t)BATCH * LIN_PAD];       // conv output fp32
__device__ int8_t   g_hb_hi[(size_t)BATCH * LIN_PAD];   // [b][l] int8 hi
__device__ int8_t   g_hb_lo[(size_t)BATCH * LIN_PAD];   // [b][l] int8 lo
__device__ float    g_vp[(size_t)KSPLIT * BATCH * T_PAD];
__device__ unsigned g_maxh;   // |h| max as fp32 bits (idempotent across runs)

// ---------------------------------------------------------------------------
// helpers
// ---------------------------------------------------------------------------
__device__ __forceinline__ uint32_t smem_u32(const void* p) {
    uint32_t a;
    asm("{ .reg .u64 t; cvta.to.shared.u64 t, %1; cvt.u32.u64 %0, t; }"
        : "=r"(a) : "l"(p));
    return a;
}

__device__ __forceinline__ void cp_async16(uint32_t dst, const void* src) {
    asm volatile("cp.async.cg.shared.global [%0], [%1], 16;"
                 :: "r"(dst), "l"(src) : "memory");
}
__device__ __forceinline__ void cp_commit() {
    asm volatile("cp.async.commit_group;" ::: "memory");
}
template <int N>
__device__ __forceinline__ void cp_wait() {
    asm volatile("cp.async.wait_group %0;" :: "n"(N) : "memory");
}

__device__ __forceinline__ void ldsm4(uint32_t& r0, uint32_t& r1,
                                      uint32_t& r2, uint32_t& r3, uint32_t addr) {
    asm volatile("ldmatrix.sync.aligned.m8n8.x4.shared.b16 {%0,%1,%2,%3}, [%4];"
                 : "=r"(r0), "=r"(r1), "=r"(r2), "=r"(r3) : "r"(addr));
}

__device__ __forceinline__ void mma_s8(int* c,
                                       uint32_t a0, uint32_t a1, uint32_t a2, uint32_t a3,
                                       uint32_t b0, uint32_t b1) {
    asm volatile(
        "mma.sync.aligned.m16n8k32.row.col.s32.s8.s8.s32 "
        "{%0,%1,%2,%3}, {%4,%5,%6,%7}, {%8,%9}, {%0,%1,%2,%3};"
        : "+r"(c[0]), "+r"(c[1]), "+r"(c[2]), "+r"(c[3])
        : "r"(a0), "r"(a1), "r"(a2), "r"(a3), "r"(b0), "r"(b1));
}

// ---------------------------------------------------------------------------
// Kernel 1: fused conv -> fp32 h + global |h| max (atomicMax on fp bits)
// grid exactly divides: 64*16128/256 = 4032 blocks, no stragglers
// ---------------------------------------------------------------------------
__global__ void conv_fuse_kernel(const float* __restrict__ x,
                                 const float* __restrict__ w1,
                                 const float* __restrict__ b1,
                                 const float* __restrict__ w2,
                                 const float* __restrict__ b2) {
    int idx = blockIdx.x * blockDim.x + threadIdx.x;
    int b = idx / LIN_PAD;
    int l = idx - b * LIN_PAD;

    float val = 0.0f;
    if (l < LIN) {
        int i = l / OW;
        int j = l - i * OW;
        const float* xp = x + (size_t)b * (HW * HW) + i * HW + j;
        float acc = b2[0];
        #pragma unroll
        for (int c = 0; c < 4; c++) {
            float s = b1[c];
            #pragma unroll
            for (int di = 0; di < 3; di++)
                #pragma unroll
                for (int dj = 0; dj < 3; dj++)
                    s = fmaf(xp[di * HW + dj], w1[c * 9 + di * 3 + dj], s);
            acc = fmaf(w2[c], fmaxf(s, 0.0f), acc);
        }
        val = acc;
    }
    g_h[idx] = val;

    // block max |val| -> atomicMax (positive floats compare as uints)
    float am = fabsf(val);
    #pragma unroll
    for (int off = 16; off > 0; off >>= 1)
        am = fmaxf(am, __shfl_xor_sync(0xFFFFFFFFu, am, off));
    __shared__ float wmax[8];
    int wid = threadIdx.x >> 5;
    if ((threadIdx.x & 31) == 0) wmax[wid] = am;
    __syncthreads();
    if (threadIdx.x == 0) {
        float m = wmax[0];
        #pragma unroll
        for (int w = 1; w < 8; w++) m = fmaxf(m, wmax[w]);
        atomicMax(&g_maxh, __float_as_uint(m));
    }
}

// ---------------------------------------------------------------------------
// Kernel 1b: quantize h -> int8 hi/lo (15-bit fixed point, global scale)
// ---------------------------------------------------------------------------
__global__ void quant_h_kernel() {
    int t = blockIdx.x * blockDim.x + threadIdx.x;   // 258048 threads, x4 vals
    float r = QF / fmaxf(__uint_as_float(g_maxh), 1e-30f);
    float4 h4 = *reinterpret_cast<const float4*>(g_h + (size_t)t * 4);
    int v0 = __float2int_rn(h4.x * r);
    int v1 = __float2int_rn(h4.y * r);
    int v2 = __float2int_rn(h4.z * r);
    int v3 = __float2int_rn(h4.w * r);
    int h0 = (v0 + 128) >> 8, h1 = (v1 + 128) >> 8;
    int h2 = (v2 + 128) >> 8, h3 = (v3 + 128) >> 8;
    int l0 = v0 - (h0 << 8), l1 = v1 - (h1 << 8);
    int l2 = v2 - (h2 << 8), l3 = v3 - (h3 << 8);
    uint32_t hp = (h0 & 0xFF) | ((h1 & 0xFF) << 8) | ((h2 & 0xFF) << 16) | (h3 << 24);
    uint32_t lp = (l0 & 0xFF) | ((l1 & 0xFF) << 8) | ((l2 & 0xFF) << 16) | (l3 << 24);
    *reinterpret_cast<uint32_t*>(g_hb_hi + (size_t)t * 4) = hp;
    *reinterpret_cast<uint32_t*>(g_hb_lo + (size_t)t * 4) = lp;
}

// ---------------------------------------------------------------------------
// GEMM device helpers (512 threads: arow = tid>>2, aq = tid&3)
// ---------------------------------------------------------------------------
__device__ __forceinline__ void ldg_a(const float* __restrict__ W,
                                      int t, int l0, int aq, bool trow_ok,
                                      float4 (&a)[4]) {
    #pragma unroll
    for (int j = 0; j < 4; j++) {
        int l = l0 + (aq * 4 + j) * 4;
        if (trow_ok && l < LIN)
            a[j] = *reinterpret_cast<const float4*>(W + (size_t)t * LIN + l);
        else
            a[j] = make_float4(0.f, 0.f, 0.f, 0.f);
    }
}

// quantize row chunk (64 vals across 4 threads) + STS int8 hi/lo + row scale
__device__ __forceinline__ void sts_a_q(char* smem, int stage, int row, int aq,
                                        const float4 (&a)[4]) {
    float m = 0.f;
    #pragma unroll
    for (int j = 0; j < 4; j++) {
        m = fmaxf(m, fmaxf(fmaxf(fabsf(a[j].x), fabsf(a[j].y)),
                           fmaxf(fabsf(a[j].z), fabsf(a[j].w))));
    }
    m = fmaxf(m, __shfl_xor_sync(0xFFFFFFFFu, m, 1));
    m = fmaxf(m, __shfl_xor_sync(0xFFFFFFFFu, m, 2));
    float r = QF / fmaxf(m, 1e-30f);

    uint32_t hiP[4], loP[4];
    #pragma unroll
    for (int j = 0; j < 4; j++) {
        int v0 = __float2int_rn(a[j].x * r);
        int v1 = __float2int_rn(a[j].y * r);
        int v2 = __float2int_rn(a[j].z * r);
        int v3 = __float2int_rn(a[j].w * r);
        int h0 = (v0 + 128) >> 8, h1 = (v1 + 128) >> 8;
        int h2 = (v2 + 128) >> 8, h3 = (v3 + 128) >> 8;
        int l0 = v0 - (h0 << 8), l1 = v1 - (h1 << 8);
        int l2 = v2 - (h2 << 8), l3 = v3 - (h3 << 8);
        hiP[j] = (h0 & 0xFF) | ((h1 & 0xFF) << 8) | ((h2 & 0xFF) << 16) | (h3 << 24);
        loP[j] = (l0 & 0xFF) | ((l1 & 0xFF) << 8) | ((l2 & 0xFF) << 16) | (l3 << 24);
    }
    uint32_t byt = (uint32_t)row * PITCH + (uint32_t)aq * 16;
    *reinterpret_cast<uint4*>(smem + A_HI(stage) + byt) =
        make_uint4(hiP[0], hiP[1], hiP[2], hiP[3]);
    *reinterpret_cast<uint4*>(smem + A_LO(stage) + byt) =
        make_uint4(loP[0], loP[1], loP[2], loP[3]);
    if (aq == 0)
        *reinterpret_cast<float*>(smem + A_SC(stage) + (uint32_t)row * 4) =
            m * (1.0f / QF);
}

__device__ __forceinline__ void cpasync_b(uint32_t sb, int st, int ktg, int tid) {
    int l0 = ktg * K_TILE;
    int id  = tid & 255;
    int row = id >> 2;                           // batch 0..63
    int ch  = id & 3;                            // 16B chunk
    uint32_t byt = (uint32_t)row * PITCH + (uint32_t)ch * 16;
    if (tid < 256)
        cp_async16(sb + B_HI(st) + byt, g_hb_hi + (size_t)row * LIN_PAD + l0 + ch * 16);
    else
        cp_async16(sb + B_LO(st) + byt, g_hb_lo + (size_t)row * LIN_PAD + l0 + ch * 16);
}

// warp tile: 32 rows (wm) x 16 cols (wn); int8 MMA k32, 2 ksteps
__device__ __forceinline__ void compute_tile_i8(char* smem, uint32_t sb,
                                                int stage, int bst,
                                                int wm, int wn, int lid,
                                                float sH, float (&accf)[2][2][4]) {
    int p1[2][2][4], p2[2][2][4];
    #pragma unroll
    for (int mt = 0; mt < 2; mt++)
        #pragma unroll
        for (int nt = 0; nt < 2; nt++)
            #pragma unroll
            for (int e = 0; e < 4; e++) { p1[mt][nt][e] = 0; p2[mt][nt][e] = 0; }

    const uint32_t lrow = (uint32_t)(lid & 15);
    const uint32_t lhi  = (uint32_t)((lid >> 4) << 4);

    uint32_t aH0 = sb + A_HI(stage) + (wm * 32 + lrow) * PITCH + lhi;
    uint32_t aH1 = aH0 + 16 * PITCH;
    uint32_t aL0 = sb + A_LO(stage) + (wm * 32 + lrow) * PITCH + lhi;
    uint32_t aL1 = aL0 + 16 * PITCH;
    uint32_t bH  = sb + B_HI(bst) + (wn * 16 + lrow) * PITCH + lhi;
    uint32_t bL  = sb + B_LO(bst) + (wn * 16 + lrow) * PITCH + lhi;

    #pragma unroll
    for (int ks = 0; ks < 2; ks++) {
        const uint32_t ko = (uint32_t)ks * 32;   // 32 int8 per kstep

        uint32_t ah[2][4], al[2][4];
        ldsm4(ah[0][0], ah[0][1], ah[0][2], ah[0][3], aH0 + ko);
        ldsm4(ah[1][0], ah[1][1], ah[1][2], ah[1][3], aH1 + ko);
        ldsm4(al[0][0], al[0][1], al[0][2], al[0][3], aL0 + ko);
        ldsm4(al[1][0], al[1][1], al[1][2], al[1][3], aL1 + ko);

        uint32_t b0, b1, b2, b3, c0, c1, c2, c3;
        ldsm4(b0, b1, b2, b3, bH + ko);
        ldsm4(c0, c1, c2, c3, bL + ko);
        uint32_t bh[2][2] = {{b0, b2}, {b1, b3}};
        uint32_t bl[2][2] = {{c0, c2}, {c1, c3}};

        #pragma unroll
        for (int mt = 0; mt < 2; mt++)
            #pragma unroll
            for (int nt = 0; nt < 2; nt++) {
                mma_s8(p1[mt][nt], ah[mt][0], ah[mt][1], ah[mt][2], ah[mt][3],
                       bh[nt][0], bh[nt][1]);
                mma_s8(p2[mt][nt], ah[mt][0], ah[mt][1], ah[mt][2], ah[mt][3],
                       bl[nt][0], bl[nt][1]);
                mma_s8(p2[mt][nt], al[mt][0], al[mt][1], al[mt][2], al[mt][3],
                       bh[nt][0], bh[nt][1]);
            }
    }

    // per-tile fp32 fixup with per-row W scale * global h scale
    const int g = lid >> 2;
    #pragma unroll
    for (int mt = 0; mt < 2; mt++) {
        int r0 = wm * 32 + mt * 16 + g;
        float s0 = *reinterpret_cast<const float*>(smem + A_SC(stage) + r0 * 4) * sH;
        float s8v = *reinterpret_cast<const float*>(smem + A_SC(stage) + (r0 + 8) * 4) * sH;
        #pragma unroll
        for (int nt = 0; nt < 2; nt++) {
            accf[mt][nt][0] += s0  * fmaf(65536.0f, (float)p1[mt][nt][0], 256.0f * (float)p2[mt][nt][0]);
            accf[mt][nt][1] += s0  * fmaf(65536.0f, (float)p1[mt][nt][1], 256.0f * (float)p2[mt][nt][1]);
            accf[mt][nt][2] += s8v * fmaf(65536.0f, (float)p1[mt][nt][2], 256.0f * (float)p2[mt][nt][2]);
            accf[mt][nt][3] += s8v * fmaf(65536.0f, (float)p1[mt][nt][3], 256.0f * (float)p2[mt][nt][3]);
        }
    }
}

// ---------------------------------------------------------------------------
// Kernel 2: int8-split IMMA GEMM, 130 CTAs x 512 threads (16 warps)
// ---------------------------------------------------------------------------
__global__ __launch_bounds__(512, 1)
void gemm_tc_kernel(const float* __restrict__ W) {
    extern __shared__ char smem[];
    const uint32_t sb = smem_u32(smem);

    const int tid = threadIdx.x;
    const int wid = tid >> 5;
    const int lid = tid & 31;
    const int g   = lid >> 2;
    const int t4  = lid & 3;
    const int wm  = wid & 3;        // 4 row groups x 32
    const int wn  = wid >> 2;       // 4 col groups x 16

    const int mtile = blockIdx.x >> 1;
    const int split = blockIdx.x & 1;
    const int t0    = mtile * 128;
    const int kt0   = split * TILES_PER_SPLIT;

    const int arow  = tid >> 2;
    const int aq    = tid & 3;
    const int atrow = t0 + arow;
    const bool trow_ok = (atrow < TRI);

    const float sH = __uint_as_float(g_maxh) * (1.0f / QF);

    float accf[2][2][4];
    #pragma unroll
    for (int i = 0; i < 2; i++)
        #pragma unroll
        for (int j = 0; j < 2; j++)
            #pragma unroll
            for (int k = 0; k < 4; k++)
                accf[i][j][k] = 0.f;

    float4 aR[4];

    // ---- prologue ----
    cpasync_b(sb, 0, kt0 + 0, tid);
    cp_commit();
    cpasync_b(sb, 1, kt0 + 1, tid);
    cp_commit();
    ldg_a(W, atrow, (kt0 + 0) * K_TILE, aq, trow_ok, aR);
    sts_a_q(smem, 0, arow, aq, aR);
    ldg_a(W, atrow, (kt0 + 1) * K_TILE, aq, trow_ok, aR);
    cp_wait<1>();
    __syncthreads();

    int bs = 0;
    for (int kt = 0; kt < TILES_PER_SPLIT; kt++) {
        const int nxt_bs = (bs + 2 >= 3) ? bs - 1 : bs + 2;

        if (kt + 2 < TILES_PER_SPLIT) {
            cpasync_b(sb, nxt_bs, kt0 + kt + 2, tid);
            cp_commit();
        }
        if (kt + 1 < TILES_PER_SPLIT)
            sts_a_q(smem, (kt + 1) & 1, arow, aq, aR);
        if (kt + 2 < TILES_PER_SPLIT)
            ldg_a(W, atrow, (kt0 + kt + 2) * K_TILE, aq, trow_ok, aR);

        compute_tile_i8(smem, sb, kt & 1, bs, wm, wn, lid, sH, accf);

        if (kt + 2 < TILES_PER_SPLIT)      cp_wait<1>();
        else if (kt + 1 < TILES_PER_SPLIT) cp_wait<0>();
        __syncthreads();

        bs = (bs + 1 >= 3) ? 0 : bs + 1;
    }

    // ---- epilogue ----
    float* vp = g_vp + (size_t)split * BATCH * T_PAD;
    #pragma unroll
    for (int mt = 0; mt < 2; mt++) {
        #pragma unroll
        for (int nt = 0; nt < 2; nt++) {
            int r  = t0 + wm * 32 + mt * 16 + g;
            int cb = wn * 16 + nt * 8 + 2 * t4;
            vp[(size_t)cb       * T_PAD + r]     = accf[mt][nt][0];
            vp[(size_t)(cb + 1) * T_PAD + r]     = accf[mt][nt][1];
            vp[(size_t)cb       * T_PAD + r + 8] = accf[mt][nt][2];
            vp[(size_t)(cb + 1) * T_PAD + r + 8] = accf[mt][nt][3];
        }
    }
}

// ---------------------------------------------------------------------------
// Kernel 3: symmetric triu scatter + split-K reduce + bias
// ---------------------------------------------------------------------------
__global__ void scatter_kernel(float* __restrict__ out,
                               const float* __restrict__ bias) {
    int idx = blockIdx.x * blockDim.x + threadIdx.x;
    if (idx >= BATCH * NDIM * NDIM) return;
    int b = idx >> 14;
    int r = (idx >> 7) & 127;
    int c = idx & 127;
    int i = min(r, c);
    int j = max(r, c);
    int t = i * NDIM - (i * (i - 1)) / 2 + (j - i);
    out[idx] = g_vp[(size_t)b * T_PAD + t] +
               g_vp[(size_t)(BATCH + b) * T_PAD + t] + bias[t];
}

// ---------------------------------------------------------------------------
extern "C" void kernel_launch(void* const* d_in, const int* in_sizes, int n_in,
                              void* d_out, int out_size) {
    const float* x       = (const float*)d_in[0];
    const float* conv1_w = (const float*)d_in[1];
    const float* conv1_b = (const float*)d_in[2];
    const float* conv2_w = (const float*)d_in[3];
    const float* conv2_b = (const float*)d_in[4];
    const float* out_w   = (const float*)d_in[5];
    const float* out_b   = (const float*)d_in[6];
    float* out = (float*)d_out;

    cudaFuncSetAttribute(gemm_tc_kernel,
                         cudaFuncAttributeMaxDynamicSharedMemorySize, SMEM_BYTES);

    conv_fuse_kernel<<<(BATCH * LIN_PAD) / 256, 256>>>(x, conv1_w, conv1_b,
                                                       conv2_w, conv2_b);
    quant_h_kernel<<<(BATCH * LIN_PAD / 4) / 256, 256>>>();
    gemm_tc_kernel<<<N_MTILES * KSPLIT, 512, SMEM_BYTES>>>(out_w);
    scatter_kernel<<<(BATCH * NDIM * NDIM + 255) / 256, 256>>>(out, out_b);
}

// round 9
// speedup vs baseline: 1.4647x; 1.4646x over previous
#include <cuda_runtime.h>
#include <cstdint>

// ---------------------------------------------------------------------------
// Problem dims
// ---------------------------------------------------------------------------
#define HW        128
#define OW        126
#define LIN       15876              // (128-2)^2
#define K_TILE    64
#define N_KTILES  252                // LIN_PAD = 16128
#define LIN_PAD   (N_KTILES * K_TILE)
#define TRI       8256
#define BATCH     64
#define NDIM      128
#define T_PAD     8320               // 65*128
#define N_MTILES  65
#define KSPLIT    2
#define TILES_PER_SPLIT (N_KTILES / KSPLIT)   // 126

// SMEM: fp32(tf32) tiles, k-grouped layout, pitch 272 B (17 chunks, odd)
// A stage: 128 x 272 = 34816, x2.  B stage: 64 x 272 = 17408, x3.
#define PITCHB    272
#define A_STG     34816u
#define A_OFF(s)  ((uint32_t)(s) * A_STG)
#define B_BASE    69632u
#define B_STG     17408u
#define B_OFF(st) (B_BASE + (uint32_t)(st) * B_STG)
#define SMEM_BYTES 121856

// ---------------------------------------------------------------------------
// Scratch (device globals — no allocation allowed)
// ---------------------------------------------------------------------------
// h, tf32-rounded, stored per 64-K-tile in k-grouped order:
// g_hq[b][kt][c], c = (k&3)*16 + (k>>2)
__device__ float g_hq[(size_t)BATCH * N_KTILES * 64];
__device__ float g_vp[(size_t)KSPLIT * BATCH * T_PAD];

// ---------------------------------------------------------------------------
// helpers
// ---------------------------------------------------------------------------
__device__ __forceinline__ uint32_t smem_u32(const void* p) {
    uint32_t a;
    asm("{ .reg .u64 t; cvta.to.shared.u64 t, %1; cvt.u32.u64 %0, t; }"
        : "=r"(a) : "l"(p));
    return a;
}

__device__ __forceinline__ void cp_async16(uint32_t dst, const void* src) {
    asm volatile("cp.async.cg.shared.global [%0], [%1], 16;"
                 :: "r"(dst), "l"(src) : "memory");
}
__device__ __forceinline__ void cp_commit() {
    asm volatile("cp.async.commit_group;" ::: "memory");
}
template <int N>
__device__ __forceinline__ void cp_wait() {
    asm volatile("cp.async.wait_group %0;" :: "n"(N) : "memory");
}

__device__ __forceinline__ uint32_t to_tf32(float x) {
    uint32_t u;
    asm("cvt.rna.tf32.f32 %0, %1;" : "=r"(u) : "f"(x));
    return u;
}

__device__ __forceinline__ void mma_tf32(float* c,
                                         uint32_t a0, uint32_t a1, uint32_t a2, uint32_t a3,
                                         uint32_t b0, uint32_t b1) {
    asm volatile(
        "mma.sync.aligned.m16n8k8.row.col.f32.tf32.tf32.f32 "
        "{%0,%1,%2,%3}, {%4,%5,%6,%7}, {%8,%9}, {%0,%1,%2,%3};"
        : "+f"(c[0]), "+f"(c[1]), "+f"(c[2]), "+f"(c[3])
        : "r"(a0), "r"(a1), "r"(a2), "r"(a3), "r"(b0), "r"(b1));
}

// ---------------------------------------------------------------------------
// Kernel 1: fused conv -> tf32-rounded h in k-grouped tile layout
// grid exactly divides: 64*16128/256 = 4032 blocks
// ---------------------------------------------------------------------------
__global__ void conv_fuse_kernel(const float* __restrict__ x,
                                 const float* __restrict__ w1,
                                 const float* __restrict__ b1,
                                 const float* __restrict__ w2,
                                 const float* __restrict__ b2) {
    int idx = blockIdx.x * blockDim.x + threadIdx.x;
    int b = idx / LIN_PAD;
    int l = idx - b * LIN_PAD;

    float val = 0.0f;
    if (l < LIN) {
        int i = l / OW;
        int j = l - i * OW;
        const float* xp = x + (size_t)b * (HW * HW) + i * HW + j;
        float acc = b2[0];
        #pragma unroll
        for (int c = 0; c < 4; c++) {
            float s = b1[c];
            #pragma unroll
            for (int di = 0; di < 3; di++)
                #pragma unroll
                for (int dj = 0; dj < 3; dj++)
                    s = fmaf(xp[di * HW + dj], w1[c * 9 + di * 3 + dj], s);
            acc = fmaf(w2[c], fmaxf(s, 0.0f), acc);
        }
        val = acc;
    }
    int kt = l >> 6;
    int k  = l & 63;
    int c  = ((k & 3) << 4) | (k >> 2);          // k-grouped column
    g_hq[((size_t)b * N_KTILES + kt) * 64 + c] = __uint_as_float(to_tf32(val));
}

// ---------------------------------------------------------------------------
// GEMM device helpers (512 threads: arow = tid>>2, aq = tid&3)
// ---------------------------------------------------------------------------
__device__ __forceinline__ void ldg_a(const float* __restrict__ W,
                                      int t, int l0, int aq, bool trow_ok,
                                      float4 (&a)[4]) {
    #pragma unroll
    for (int j = 0; j < 4; j++) {
        int l = l0 + (aq * 4 + j) * 4;
        if (trow_ok && l < LIN)
            a[j] = *reinterpret_cast<const float4*>(W + (size_t)t * LIN + l);
        else
            a[j] = make_float4(0.f, 0.f, 0.f, 0.f);
    }
}

// convert to tf32 + store in k-grouped layout.
// thread owns k = aq*16 + (j*4 + comp). col(k) = (k&3)*16 + (k>>2)
//  -> float4 m (m = k&3) at col m*16 + aq*4 holds j = 0..3 of comp m.
__device__ __forceinline__ void sts_a_tf32(char* smem, int stage, int row, int aq,
                                           const float4 (&a)[4]) {
    uint32_t u[4][4];
    #pragma unroll
    for (int j = 0; j < 4; j++) {
        u[j][0] = to_tf32(a[j].x);
        u[j][1] = to_tf32(a[j].y);
        u[j][2] = to_tf32(a[j].z);
        u[j][3] = to_tf32(a[j].w);
    }
    uint32_t base = A_OFF(stage) + (uint32_t)row * PITCHB + (uint32_t)aq * 16;
    #pragma unroll
    for (int m = 0; m < 4; m++) {
        *reinterpret_cast<uint4*>(smem + base + (uint32_t)m * 64) =
            make_uint4(u[0][m], u[1][m], u[2][m], u[3][m]);
    }
}

// B tile: 64 rows x 64 floats (already tf32 + k-grouped in gmem). 1024 chunks.
__device__ __forceinline__ void cpasync_b(uint32_t sb, int st, int ktg, int tid) {
    #pragma unroll
    for (int i = 0; i < 2; i++) {
        int cid = tid + i * 512;
        int row = cid >> 4;
        int ch  = cid & 15;
        uint32_t dst = sb + B_OFF(st) + (uint32_t)row * PITCHB + (uint32_t)ch * 16;
        cp_async16(dst, g_hq + ((size_t)row * N_KTILES + ktg) * 64 + ch * 4);
    }
}

// warp tile 32(m) x 16(n), K=64 via 8 ksteps of m16n8k8 (32 MMAs)
__device__ __forceinline__ void compute_tile(char* smem, int stage, int bst,
                                             int wm, int wn, int lid,
                                             float (&acc)[2][2][4]) {
    const int lrow = lid >> 2;
    const int t4   = lid & 3;

    const char* aB = smem + A_OFF(stage) + (wm * 32 + lrow) * PITCHB + t4 * 64;
    const char* bB = smem + B_OFF(bst)   + (wn * 16 + lrow) * PITCHB + t4 * 64;

    #pragma unroll
    for (int q = 0; q < 4; q++) {
        const uint32_t qo = (uint32_t)q * 16;
        uint4 A0 = *reinterpret_cast<const uint4*>(aB + qo);
        uint4 A1 = *reinterpret_cast<const uint4*>(aB + 8 * PITCHB + qo);
        uint4 A2 = *reinterpret_cast<const uint4*>(aB + 16 * PITCHB + qo);
        uint4 A3 = *reinterpret_cast<const uint4*>(aB + 24 * PITCHB + qo);
        uint4 B0 = *reinterpret_cast<const uint4*>(bB + qo);
        uint4 B1 = *reinterpret_cast<const uint4*>(bB + 8 * PITCHB + qo);

        // kstep 2q  : components .x (k), .y (k+4)
        mma_tf32(acc[0][0], A0.x, A1.x, A0.y, A1.y, B0.x, B0.y);
        mma_tf32(acc[0][1], A0.x, A1.x, A0.y, A1.y, B1.x, B1.y);
        mma_tf32(acc[1][0], A2.x, A3.x, A2.y, A3.y, B0.x, B0.y);
        mma_tf32(acc[1][1], A2.x, A3.x, A2.y, A3.y, B1.x, B1.y);
        // kstep 2q+1: components .z, .w
        mma_tf32(acc[0][0], A0.z, A1.z, A0.w, A1.w, B0.z, B0.w);
        mma_tf32(acc[0][1], A0.z, A1.z, A0.w, A1.w, B1.z, B1.w);
        mma_tf32(acc[1][0], A2.z, A3.z, A2.w, A3.w, B0.z, B0.w);
        mma_tf32(acc[1][1], A2.z, A3.z, A2.w, A3.w, B1.z, B1.w);
    }
}

// ---------------------------------------------------------------------------
// Kernel 2: 1xTF32 GEMM, 130 CTAs x 512 threads (16 warps)
// A double-buffered, B triple-buffered, one barrier per tile.
// ---------------------------------------------------------------------------
__global__ __launch_bounds__(512, 1)
void gemm_tc_kernel(const float* __restrict__ W) {
    extern __shared__ char smem[];
    const uint32_t sb = smem_u32(smem);

    const int tid = threadIdx.x;
    const int wid = tid >> 5;
    const int lid = tid & 31;
    const int g   = lid >> 2;
    const int t4  = lid & 3;
    const int wm  = wid & 3;        // 4 row groups x 32
    const int wn  = wid >> 2;       // 4 col groups x 16

    const int mtile = blockIdx.x >> 1;
    const int split = blockIdx.x & 1;
    const int t0    = mtile * 128;
    const int kt0   = split * TILES_PER_SPLIT;

    const int arow  = tid >> 2;
    const int aq    = tid & 3;
    const int atrow = t0 + arow;
    const bool trow_ok = (atrow < TRI);

    float acc[2][2][4];
    #pragma unroll
    for (int i = 0; i < 2; i++)
        #pragma unroll
        for (int j = 0; j < 2; j++)
            #pragma unroll
            for (int k = 0; k < 4; k++)
                acc[i][j][k] = 0.f;

    float4 aR[4];

    // ---- prologue ----
    cpasync_b(sb, 0, kt0 + 0, tid);
    cp_commit();
    cpasync_b(sb, 1, kt0 + 1, tid);
    cp_commit();
    ldg_a(W, atrow, (kt0 + 0) * K_TILE, aq, trow_ok, aR);
    sts_a_tf32(smem, 0, arow, aq, aR);
    ldg_a(W, atrow, (kt0 + 1) * K_TILE, aq, trow_ok, aR);
    cp_wait<1>();
    __syncthreads();

    int bs = 0;
    for (int kt = 0; kt < TILES_PER_SPLIT; kt++) {
        const int nxt_bs = (bs + 2 >= 3) ? bs - 1 : bs + 2;

        if (kt + 2 < TILES_PER_SPLIT) {
            cpasync_b(sb, nxt_bs, kt0 + kt + 2, tid);
            cp_commit();
        }
        if (kt + 1 < TILES_PER_SPLIT)
            sts_a_tf32(smem, (kt + 1) & 1, arow, aq, aR);
        if (kt + 2 < TILES_PER_SPLIT)
            ldg_a(W, atrow, (kt0 + kt + 2) * K_TILE, aq, trow_ok, aR);

        compute_tile(smem, kt & 1, bs, wm, wn, lid, acc);

        if (kt + 2 < TILES_PER_SPLIT)      cp_wait<1>();
        else if (kt + 1 < TILES_PER_SPLIT) cp_wait<0>();
        __syncthreads();

        bs = (bs + 1 >= 3) ? 0 : bs + 1;
    }

    // ---- epilogue: C frag rows g, g+8; cols 2*t4, 2*t4+1 ----
    float* vp = g_vp + (size_t)split * BATCH * T_PAD;
    #pragma unroll
    for (int mt = 0; mt < 2; mt++) {
        #pragma unroll
        for (int nt = 0; nt < 2; nt++) {
            int r  = t0 + wm * 32 + mt * 16 + g;
            int cb = wn * 16 + nt * 8 + 2 * t4;
            vp[(size_t)cb       * T_PAD + r]     = acc[mt][nt][0];
            vp[(size_t)(cb + 1) * T_PAD + r]     = acc[mt][nt][1];
            vp[(size_t)cb       * T_PAD + r + 8] = acc[mt][nt][2];
            vp[(size_t)(cb + 1) * T_PAD + r + 8] = acc[mt][nt][3];
        }
    }
}

// ---------------------------------------------------------------------------
// Kernel 3: symmetric triu scatter + split-K reduce + bias
// ---------------------------------------------------------------------------
__global__ void scatter_kernel(float* __restrict__ out,
                               const float* __restrict__ bias) {
    int idx = blockIdx.x * blockDim.x + threadIdx.x;
    if (idx >= BATCH * NDIM * NDIM) return;
    int b = idx >> 14;
    int r = (idx >> 7) & 127;
    int c = idx & 127;
    int i = min(r, c);
    int j = max(r, c);
    int t = i * NDIM - (i * (i - 1)) / 2 + (j - i);
    out[idx] = g_vp[(size_t)b * T_PAD + t] +
               g_vp[(size_t)(BATCH + b) * T_PAD + t] + bias[t];
}

// ---------------------------------------------------------------------------
extern "C" void kernel_launch(void* const* d_in, const int* in_sizes, int n_in,
                              void* d_out, int out_size) {
    const float* x       = (const float*)d_in[0];
    const float* conv1_w = (const float*)d_in[1];
    const float* conv1_b = (const float*)d_in[2];
    const float* conv2_w = (const float*)d_in[3];
    const float* conv2_b = (const float*)d_in[4];
    const float* out_w   = (const float*)d_in[5];
    const float* out_b   = (const float*)d_in[6];
    float* out = (float*)d_out;

    cudaFuncSetAttribute(gemm_tc_kernel,
                         cudaFuncAttributeMaxDynamicSharedMemorySize, SMEM_BYTES);

    conv_fuse_kernel<<<(BATCH * LIN_PAD) / 256, 256>>>(x, conv1_w, conv1_b,
                                                       conv2_w, conv2_b);
    gemm_tc_kernel<<<N_MTILES * KSPLIT, 512, SMEM_BYTES>>>(out_w);
    scatter_kernel<<<(BATCH * NDIM * NDIM + 255) / 256, 256>>>(out, out_b);
}

// round 10
// speedup vs baseline: 3.3645x; 2.2971x over previous
#include <cuda_runtime.h>
#include <cuda_fp16.h>
#include <cstdint>

// ---------------------------------------------------------------------------
// Problem dims
// ---------------------------------------------------------------------------
#define HW        128
#define OW        126
#define LIN       15876              // (128-2)^2
#define K_TILE    64
#define N_KTILES  252                // LIN_PAD = 16128
#define LIN_PAD   (N_KTILES * K_TILE)
#define TRI       8256
#define BATCH     64
#define NDIM      128
#define T_PAD     8320               // 65*128
#define N_MTILES  65
#define KSPLIT    2
#define TILES_PER_SPLIT (N_KTILES / KSPLIT)   // 126

// SMEM layout, pitch 144 B (conflict-free ldmatrix, proven in R6).
// A stage: 128 x 144 = 18432 (fp16, single), x2
// B stage:  64 x 144 =  9216 (fp16, single), x3
#define A_PITCH   144
#define A_STG     18432u
#define A_OFF(s)  ((uint32_t)(s) * A_STG)
#define B_BASE    36864u
#define B_STG     9216u
#define B_OFF(st) (B_BASE + (uint32_t)(st) * B_STG)
#define SMEM_BYTES 64512

// ---------------------------------------------------------------------------
// Scratch (device globals — no allocation allowed)
// ---------------------------------------------------------------------------
__device__ __half g_hb[(size_t)BATCH * LIN_PAD];   // [b][l] fp16 h
__device__ float  g_vp[(size_t)KSPLIT * BATCH * T_PAD];

// ---------------------------------------------------------------------------
// helpers
// ---------------------------------------------------------------------------
__device__ __forceinline__ uint32_t smem_u32(const void* p) {
    uint32_t a;
    asm("{ .reg .u64 t; cvta.to.shared.u64 t, %1; cvt.u32.u64 %0, t; }"
        : "=r"(a) : "l"(p));
    return a;
}

__device__ __forceinline__ void cp_async16(uint32_t dst, const void* src) {
    asm volatile("cp.async.cg.shared.global [%0], [%1], 16;"
                 :: "r"(dst), "l"(src) : "memory");
}
__device__ __forceinline__ void cp_commit() {
    asm volatile("cp.async.commit_group;" ::: "memory");
}
template <int N>
__device__ __forceinline__ void cp_wait() {
    asm volatile("cp.async.wait_group %0;" :: "n"(N) : "memory");
}

__device__ __forceinline__ void ldsm4(uint32_t& r0, uint32_t& r1,
                                      uint32_t& r2, uint32_t& r3, uint32_t addr) {
    asm volatile("ldmatrix.sync.aligned.m8n8.x4.shared.b16 {%0,%1,%2,%3}, [%4];"
                 : "=r"(r0), "=r"(r1), "=r"(r2), "=r"(r3) : "r"(addr));
}

__device__ __forceinline__ void mma_f16(float* c,
                                        uint32_t a0, uint32_t a1, uint32_t a2, uint32_t a3,
                                        uint32_t b0, uint32_t b1) {
    asm volatile(
        "mma.sync.aligned.m16n8k16.row.col.f32.f16.f16.f32 "
        "{%0,%1,%2,%3}, {%4,%5,%6,%7}, {%8,%9}, {%0,%1,%2,%3};"
        : "+f"(c[0]), "+f"(c[1]), "+f"(c[2]), "+f"(c[3])
        : "r"(a0), "r"(a1), "r"(a2), "r"(a3), "r"(b0), "r"(b1));
}

__device__ __forceinline__ uint32_t pack_h2(float x, float y) {
    __half2 h = __floats2half2_rn(x, y);
    return *reinterpret_cast<uint32_t*>(&h);
}

// ---------------------------------------------------------------------------
// Kernel 1: fused conv -> fp16 h, [b][l] layout (pad rows zero)
// grid exactly divides: 64*16128/256 = 4032 blocks
// ---------------------------------------------------------------------------
__global__ void conv_fuse_kernel(const float* __restrict__ x,
                                 const float* __restrict__ w1,
                                 const float* __restrict__ b1,
                                 const float* __restrict__ w2,
                                 const float* __restrict__ b2) {
    int idx = blockIdx.x * blockDim.x + threadIdx.x;
    int b = idx / LIN_PAD;
    int l = idx - b * LIN_PAD;

    float val = 0.0f;
    if (l < LIN) {
        int i = l / OW;
        int j = l - i * OW;
        const float* xp = x + (size_t)b * (HW * HW) + i * HW + j;
        float acc = b2[0];
        #pragma unroll
        for (int c = 0; c < 4; c++) {
            float s = b1[c];
            #pragma unroll
            for (int di = 0; di < 3; di++)
                #pragma unroll
                for (int dj = 0; dj < 3; dj++)
                    s = fmaf(xp[di * HW + dj], w1[c * 9 + di * 3 + dj], s);
            acc = fmaf(w2[c], fmaxf(s, 0.0f), acc);
        }
        val = acc;
    }
    g_hb[idx] = __float2half(val);
}

// ---------------------------------------------------------------------------
// GEMM device helpers (512 threads: arow = tid>>2, aq = tid&3)
// ---------------------------------------------------------------------------
__device__ __forceinline__ void ldg_a(const float* __restrict__ W,
                                      int t, int l0, int aq, bool trow_ok,
                                      float4 (&a)[4]) {
    #pragma unroll
    for (int j = 0; j < 4; j++) {
        int l = l0 + (aq * 4 + j) * 4;
        if (trow_ok && l < LIN)
            a[j] = *reinterpret_cast<const float4*>(W + (size_t)t * LIN + l);
        else
            a[j] = make_float4(0.f, 0.f, 0.f, 0.f);
    }
}

__device__ __forceinline__ void sts_a(char* smem, int stage, int row, int aq,
                                      const float4 (&a)[4]) {
    #pragma unroll
    for (int j = 0; j < 4; j++) {
        uint32_t byt = A_OFF(stage) + (uint32_t)row * A_PITCH +
                       (uint32_t)(aq * 4 + j) * 8;
        *reinterpret_cast<uint2*>(smem + byt) =
            make_uint2(pack_h2(a[j].x, a[j].y), pack_h2(a[j].z, a[j].w));
    }
}

// B tile: 64 rows x 128 B = 512 chunks, one cp.async per thread
__device__ __forceinline__ void cpasync_b(uint32_t sb, int st, int ktg, int tid) {
    int row = tid >> 3;                          // batch 0..63
    int ch  = tid & 7;                           // 16B chunk
    uint32_t dst = sb + B_OFF(st) + (uint32_t)row * A_PITCH + (uint32_t)ch * 16;
    cp_async16(dst, g_hb + (size_t)row * LIN_PAD + ktg * K_TILE + ch * 8);
}

// warp tile 32(m) x 16(n): 4 ksteps x (2 ldsm A + 1 ldsm B + 4 MMA)
__device__ __forceinline__ void compute_tile(uint32_t sb, int stage, int bst,
                                             int wm, int wn, int lid,
                                             float (&acc)[2][2][4]) {
    const uint32_t lrow = (uint32_t)(lid & 15);
    const uint32_t lhi  = (uint32_t)((lid >> 4) << 4);

    uint32_t aH0 = sb + A_OFF(stage) + (wm * 32 + lrow) * A_PITCH + lhi;
    uint32_t aH1 = aH0 + 16 * A_PITCH;
    uint32_t bH  = sb + B_OFF(bst) + (wn * 16 + lrow) * A_PITCH + lhi;

    #pragma unroll
    for (int ks = 0; ks < 4; ks++) {
        const uint32_t ko = (uint32_t)ks * 32;   // 16 fp16 = 32 B per kstep

        uint32_t a0[4], a1[4];
        ldsm4(a0[0], a0[1], a0[2], a0[3], aH0 + ko);
        ldsm4(a1[0], a1[1], a1[2], a1[3], aH1 + ko);

        uint32_t b0, b1, b2, b3;
        ldsm4(b0, b1, b2, b3, bH + ko);          // frag0 n0-7, frag1 n8-15

        mma_f16(acc[0][0], a0[0], a0[1], a0[2], a0[3], b0, b2);
        mma_f16(acc[0][1], a0[0], a0[1], a0[2], a0[3], b1, b3);
        mma_f16(acc[1][0], a1[0], a1[1], a1[2], a1[3], b0, b2);
        mma_f16(acc[1][1], a1[0], a1[1], a1[2], a1[3], b1, b3);
    }
}

// ---------------------------------------------------------------------------
// Kernel 2: fp16 HMMA GEMM, 130 CTAs x 512 threads (16 warps)
// A double-buffered, B triple-buffered, one barrier per tile.
// ---------------------------------------------------------------------------
__global__ __launch_bounds__(512, 1)
void gemm_tc_kernel(const float* __restrict__ W) {
    extern __shared__ char smem[];
    const uint32_t sb = smem_u32(smem);

    const int tid = threadIdx.x;
    const int wid = tid >> 5;
    const int lid = tid & 31;
    const int g   = lid >> 2;
    const int t4  = lid & 3;
    const int wm  = wid & 3;        // 4 row groups x 32
    const int wn  = wid >> 2;       // 4 col groups x 16

    const int mtile = blockIdx.x >> 1;
    const int split = blockIdx.x & 1;
    const int t0    = mtile * 128;
    const int kt0   = split * TILES_PER_SPLIT;

    const int arow  = tid >> 2;
    const int aq    = tid & 3;
    const int atrow = t0 + arow;
    const bool trow_ok = (atrow < TRI);

    float acc[2][2][4];
    #pragma unroll
    for (int i = 0; i < 2; i++)
        #pragma unroll
        for (int j = 0; j < 2; j++)
            #pragma unroll
            for (int k = 0; k < 4; k++)
                acc[i][j][k] = 0.f;

    float4 aR[4];

    // ---- prologue ----
    cpasync_b(sb, 0, kt0 + 0, tid);
    cp_commit();
    cpasync_b(sb, 1, kt0 + 1, tid);
    cp_commit();
    ldg_a(W, atrow, (kt0 + 0) * K_TILE, aq, trow_ok, aR);
    sts_a(smem, 0, arow, aq, aR);
    ldg_a(W, atrow, (kt0 + 1) * K_TILE, aq, trow_ok, aR);
    cp_wait<1>();
    __syncthreads();

    int bs = 0;
    for (int kt = 0; kt < TILES_PER_SPLIT; kt++) {
        const int nxt_bs = (bs + 2 >= 3) ? bs - 1 : bs + 2;

        if (kt + 2 < TILES_PER_SPLIT) {
            cpasync_b(sb, nxt_bs, kt0 + kt + 2, tid);
            cp_commit();
        }
        if (kt + 1 < TILES_PER_SPLIT)
            sts_a(smem, (kt + 1) & 1, arow, aq, aR);
        if (kt + 2 < TILES_PER_SPLIT)
            ldg_a(W, atrow, (kt0 + kt + 2) * K_TILE, aq, trow_ok, aR);

        compute_tile(sb, kt & 1, bs, wm, wn, lid, acc);

        if (kt + 2 < TILES_PER_SPLIT)      cp_wait<1>();
        else if (kt + 1 < TILES_PER_SPLIT) cp_wait<0>();
        __syncthreads();

        bs = (bs + 1 >= 3) ? 0 : bs + 1;
    }

    // ---- epilogue ----
    float* vp = g_vp + (size_t)split * BATCH * T_PAD;
    #pragma unroll
    for (int mt = 0; mt < 2; mt++) {
        #pragma unroll
        for (int nt = 0; nt < 2; nt++) {
            int r  = t0 + wm * 32 + mt * 16 + g;
            int cb = wn * 16 + nt * 8 + 2 * t4;
            vp[(size_t)cb       * T_PAD + r]     = acc[mt][nt][0];
            vp[(size_t)(cb + 1) * T_PAD + r]     = acc[mt][nt][1];
            vp[(size_t)cb       * T_PAD + r + 8] = acc[mt][nt][2];
            vp[(size_t)(cb + 1) * T_PAD + r + 8] = acc[mt][nt][3];
        }
    }
}

// ---------------------------------------------------------------------------
// Kernel 3: symmetric triu scatter + split-K reduce + bias
// ---------------------------------------------------------------------------
__global__ void scatter_kernel(float* __restrict__ out,
                               const float* __restrict__ bias) {
    int idx = blockIdx.x * blockDim.x + threadIdx.x;
    if (idx >= BATCH * NDIM * NDIM) return;
    int b = idx >> 14;
    int r = (idx >> 7) & 127;
    int c = idx & 127;
    int i = min(r, c);
    int j = max(r, c);
    int t = i * NDIM - (i * (i - 1)) / 2 + (j - i);
    out[idx] = g_vp[(size_t)b * T_PAD + t] +
               g_vp[(size_t)(BATCH + b) * T_PAD + t] + bias[t];
}

// ---------------------------------------------------------------------------
extern "C" void kernel_launch(void* const* d_in, const int* in_sizes, int n_in,
                              void* d_out, int out_size) {
    const float* x       = (const float*)d_in[0];
    const float* conv1_w = (const float*)d_in[1];
    const float* conv1_b = (const float*)d_in[2];
    const float* conv2_w = (const float*)d_in[3];
    const float* conv2_b = (const float*)d_in[4];
    const float* out_w   = (const float*)d_in[5];
    const float* out_b   = (const float*)d_in[6];
    float* out = (float*)d_out;

    cudaFuncSetAttribute(gemm_tc_kernel,
                         cudaFuncAttributeMaxDynamicSharedMemorySize, SMEM_BYTES);

    conv_fuse_kernel<<<(BATCH * LIN_PAD) / 256, 256>>>(x, conv1_w, conv1_b,
                                                       conv2_w, conv2_b);
    gemm_tc_kernel<<<N_MTILES * KSPLIT, 512, SMEM_BYTES>>>(out_w);
    scatter_kernel<<<(BATCH * NDIM * NDIM + 255) / 256, 256>>>(out, out_b);
}